// round 2
// baseline (speedup 1.0000x reference)
#include <cuda_runtime.h>

#define VOCABN  100000
#define EMB     256
#define NS      256
#define BATCHN  16384
#define ROWS    32
#define NTHR    256
#define NBLK    (BATCHN / ROWS)

__device__ int   g_is64;
__device__ float g_partial[NBLK];

__device__ __forceinline__ int load_idx(const void* p, int i, int is64) {
    return is64 ? (int)__ldg(&((const long long*)p)[i]) : __ldg(&((const int*)p)[i]);
}

// log(NS * prob(id)) computed exactly like the reference (f32 log difference,
// including its cancellation behavior) so we track its rounding.
__device__ __forceinline__ float log_adj(int id) {
    float fid = (float)id;
    float num = logf(fid + 2.0f) - logf(fid + 1.0f);
    float p   = num / logf((float)VOCABN + 1.0f);
    return logf((float)NS * p);
}

__device__ __forceinline__ float xent_pos(float l) {   // label = 1
    return fmaxf(l, 0.0f) - l + log1pf(expf(-fabsf(l)));
}
__device__ __forceinline__ float xent_neg(float l) {   // label = 0
    return fmaxf(l, 0.0f) + log1pf(expf(-fabsf(l)));
}

// Detect whether index arrays are int64 (odd 32-bit words all zero) or int32.
__global__ void k_detect(const unsigned int* w) {
    int t = threadIdx.x;
    unsigned int hi = w[2 * t + 1];
    unsigned int b = __ballot_sync(0xFFFFFFFFu, hi == 0u);
    if (t == 0) g_is64 = (b == 0xFFFFFFFFu) ? 1 : 0;
}

__global__ __launch_bounds__(NTHR) void k_main(
    const float* __restrict__ emb, const float* __restrict__ Wnce,
    const float* __restrict__ bias, const void* __restrict__ inp,
    const void* __restrict__ lab, const void* __restrict__ samp,
    float* __restrict__ out)
{
    extern __shared__ float sm[];
    float* Es     = sm;                       // [ROWS][EMB]
    float* Ws     = sm + ROWS * EMB;          // [NS][33]  (+1 pad: conflict-free)
    float* sbadj  = Ws + NS * 33;             // [NS]
    float* truep  = sbadj + NS;               // [ROWS]
    float* rowsum = truep + ROWS;             // [8][ROWS]
    int*   sidx   = (int*)(rowsum + 8 * ROWS);// [NS]
    int*   ridx   = sidx + NS;                // [ROWS]
    int*   lidx   = ridx + ROWS;              // [ROWS]

    const int t    = threadIdx.x;
    const int w    = t >> 5;
    const int lane = t & 31;
    const int b0   = blockIdx.x * ROWS;
    const int is64 = g_is64;

    if (t < ROWS) {
        ridx[t] = load_idx(inp, b0 + t, is64);
        lidx[t] = load_idx(lab, b0 + t, is64);
    }
    {
        int sid = load_idx(samp, t, is64);
        sidx[t]  = sid;
        sbadj[t] = __ldg(&bias[sid]) - log_adj(sid);
    }
    __syncthreads();

    // ---- Gather embed rows -> smem tile + d_out (float4, coalesced) ----
    {
        const float4* e4 = (const float4*)emb;
        float4* o4 = (float4*)out;
        #pragma unroll
        for (int i = 0; i < (ROWS * EMB / 4) / NTHR; i++) {   // 8 iters
            int lid = i * NTHR + t;
            int r = lid >> 6;        // EMB/4 = 64 float4 per row
            int c = lid & 63;
            float4 v = e4[(size_t)ridx[r] * (EMB / 4) + c];
            ((float4*)(Es + r * EMB))[c] = v;
            o4[(size_t)(b0 + r) * (EMB / 4) + c] = v;
        }
    }
    __syncthreads();

    // ---- True logits: warp w handles rows 4w..4w+3 ----
    #pragma unroll
    for (int rr = 0; rr < 4; rr++) {
        int r = w * 4 + rr;
        int lblv = lidx[r];
        const float4* wr = (const float4*)(Wnce + (size_t)lblv * EMB);
        const float4* er = (const float4*)(Es + r * EMB);
        float s = 0.0f;
        #pragma unroll
        for (int j = 0; j < 2; j++) {
            float4 a = __ldg(&wr[lane + 32 * j]);
            float4 b = er[lane + 32 * j];
            s += a.x * b.x + a.y * b.y + a.z * b.z + a.w * b.w;
        }
        #pragma unroll
        for (int o = 16; o; o >>= 1) s += __shfl_xor_sync(0xFFFFFFFFu, s, o);
        if (lane == 0) {
            float l = s + __ldg(&bias[lblv]) - log_adj(lblv);
            truep[r] = xent_pos(l);
        }
    }

    // ---- Sampled GEMM: thread t owns sampled column t, 32 rows ----
    float acc[ROWS];
    #pragma unroll
    for (int r = 0; r < ROWS; r++) acc[r] = 0.0f;

    for (int c0 = 0; c0 < EMB; c0 += 32) {
        __syncthreads();
        // Stage W chunk [256 x 32] (coalesced LDG, padded STS)
        #pragma unroll
        for (int i = 0; i < 32; i++) {
            int s = i * 8 + w;
            Ws[s * 33 + lane] = __ldg(&Wnce[(size_t)sidx[s] * EMB + c0 + lane]);
        }
        __syncthreads();
        #pragma unroll
        for (int k4 = 0; k4 < 8; k4++) {
            float w0 = Ws[t * 33 + k4 * 4 + 0];
            float w1 = Ws[t * 33 + k4 * 4 + 1];
            float w2 = Ws[t * 33 + k4 * 4 + 2];
            float w3 = Ws[t * 33 + k4 * 4 + 3];
            #pragma unroll
            for (int r = 0; r < ROWS; r++) {
                float4 e = ((const float4*)(Es + r * EMB))[(c0 >> 2) + k4];
                acc[r] = fmaf(e.x, w0, acc[r]);
                acc[r] = fmaf(e.y, w1, acc[r]);
                acc[r] = fmaf(e.z, w2, acc[r]);
                acc[r] = fmaf(e.w, w3, acc[r]);
            }
        }
    }

    // ---- xent over sampled logits, reduce across 256 columns per row ----
    {
        float badj = sbadj[t];
        #pragma unroll
        for (int r = 0; r < ROWS; r++) {
            float v = xent_neg(acc[r] + badj);
            #pragma unroll
            for (int o = 16; o; o >>= 1) v += __shfl_xor_sync(0xFFFFFFFFu, v, o);
            if (lane == 0) rowsum[w * ROWS + r] = v;
        }
    }
    __syncthreads();
    if (t < ROWS) {
        float s = truep[t];
        #pragma unroll
        for (int ww = 0; ww < 8; ww++) s += rowsum[ww * ROWS + t];
        #pragma unroll
        for (int o = 16; o; o >>= 1) s += __shfl_xor_sync(0xFFFFFFFFu, s, o);
        if (t == 0) g_partial[blockIdx.x] = s;
    }
}

// Deterministic fixed-order final reduction; cost goes in the last output slot.
__global__ void k_fin(float* __restrict__ out, int out_size) {
    __shared__ float ssum[8];
    int t = threadIdx.x;
    float s = g_partial[t] + g_partial[t + 256];
    #pragma unroll
    for (int o = 16; o; o >>= 1) s += __shfl_xor_sync(0xFFFFFFFFu, s, o);
    if ((t & 31) == 0) ssum[t >> 5] = s;
    __syncthreads();
    if (t == 0) {
        float tot = 0.0f;
        #pragma unroll
        for (int i = 0; i < 8; i++) tot += ssum[i];
        out[out_size - 1] = tot / (float)BATCHN;
    }
}

extern "C" void kernel_launch(void* const* d_in, const int* in_sizes, int n_in,
                              void* d_out, int out_size) {
    const float* emb  = (const float*)d_in[0];
    const float* Wnce = (const float*)d_in[1];
    const float* bias = (const float*)d_in[2];
    const void*  inp  = d_in[3];
    const void*  lab  = d_in[4];
    const void*  samp = d_in[5];
    float* out = (float*)d_out;

    const int smem_bytes =
        (ROWS * EMB + NS * 33 + NS + ROWS + 8 * ROWS) * 4   // floats
        + (NS + 2 * ROWS) * 4;                              // ints
    cudaFuncSetAttribute(k_main, cudaFuncAttributeMaxDynamicSharedMemorySize, smem_bytes);

    k_detect<<<1, 32>>>((const unsigned int*)inp);
    k_main<<<NBLK, NTHR, smem_bytes>>>(emb, Wnce, bias, inp, lab, samp, out);
    k_fin<<<1, 256>>>(out, out_size);
}

// round 6
// speedup vs baseline: 3.2836x; 3.2836x over previous
#include <cuda_runtime.h>
#include <cuda_bf16.h>
#include <cstdint>

#define VOCABN  100000
#define EMB     256
#define NS      256
#define BATCHN  16384
#define MROWS   128
#define NTHR    256
#define NBLK    (BATCHN / MROWS)   // 128

#define STRIDE  528                 // bytes per smem row: 264 bf16 (256 + 8 pad)

// ---- smem byte offsets ----
#define OFF_A     0                 // bf16 A [128][264]        67584 B
#define OFF_B     67584             // bf16 B [256][264]       135168 B
#define OFF_SBADJ 202752            // f32[256] bias - log(NS*p)
#define OFF_TRUEP 203776            // f32[128] xent_pos(true logit)
#define OFF_ROWH  204288            // f32[2][128] per-N-half row sums
#define OFF_SIDX  205312            // i32[256]
#define OFF_RIDX  206336            // i32[128]
#define OFF_LIDX  206848            // i32[128]
#define OFF_WSUM  207360            // f32[4]
#define OFF_IS64  207376            // i32
#define SMEM_BYTES 207424

__device__ float g_partial[NBLK];

static __device__ __forceinline__ uint32_t smem_u32(const void* p) {
    uint32_t a;
    asm("{ .reg .u64 t; cvta.to.shared.u64 t, %1; cvt.u32.u64 %0, t; }" : "=r"(a) : "l"(p));
    return a;
}
static __device__ __forceinline__ uint32_t pack_bf16(float lo, float hi) {
    uint32_t r;
    asm("cvt.rn.bf16x2.f32 %0, %1, %2;" : "=r"(r) : "f"(hi), "f"(lo));
    return r;
}
static __device__ __forceinline__ void st4bf16(uint32_t addr, float4 v) {
    uint32_t lo = pack_bf16(v.x, v.y), hi = pack_bf16(v.z, v.w);
    asm volatile("st.shared.v2.b32 [%0], {%1, %2};" :: "r"(addr), "r"(lo), "r"(hi));
}
static __device__ __forceinline__ uint32_t lds32(uint32_t a) {
    uint32_t v; asm volatile("ld.shared.b32 %0, [%1];" : "=r"(v) : "r"(a)); return v;
}
static __device__ __forceinline__ float2 lds64f(uint32_t a) {
    float2 v; asm volatile("ld.shared.v2.f32 {%0, %1}, [%2];" : "=f"(v.x), "=f"(v.y) : "r"(a));
    return v;
}
#define MMA16816(d, a, b)                                                     \
    asm volatile("mma.sync.aligned.m16n8k16.row.col.f32.bf16.bf16.f32 "       \
                 "{%0,%1,%2,%3}, {%4,%5,%6,%7}, {%8,%9}, {%0,%1,%2,%3};"      \
                 : "+f"((d)[0]), "+f"((d)[1]), "+f"((d)[2]), "+f"((d)[3])     \
                 : "r"((a)[0]), "r"((a)[1]), "r"((a)[2]), "r"((a)[3]),        \
                   "r"((b)[0]), "r"((b)[1]))

static __device__ __forceinline__ int load_idx(const void* p, int i, int is64) {
    return is64 ? (int)__ldg(&((const long long*)p)[i]) : __ldg(&((const int*)p)[i]);
}
// log(NS * prob(id)) exactly like the reference (f32 log difference)
static __device__ __forceinline__ float log_adj(int id) {
    float fid = (float)id;
    float num = logf(fid + 2.0f) - logf(fid + 1.0f);
    return logf((float)NS * (num / logf((float)VOCABN + 1.0f)));
}
static __device__ __forceinline__ float xent_neg(float l) {     // label = 0
    return fmaxf(l, 0.0f) + log1pf(__expf(-fabsf(l)));
}

__global__ __launch_bounds__(NTHR, 1) void k_main(
    const float* __restrict__ emb, const float* __restrict__ Wnce,
    const float* __restrict__ bias, const void* __restrict__ inp,
    const void* __restrict__ lab, const void* __restrict__ samp,
    float* __restrict__ out)
{
    extern __shared__ char smp[];
    const uint32_t sb = smem_u32(smp);

    const int t    = threadIdx.x;
    const int w    = t >> 5;
    const int lane = t & 31;
    const int tq   = lane >> 2;      // 0..7
    const int tr   = lane & 3;       // 0..3
    const int b0   = blockIdx.x * MROWS;

    float* sbadj = (float*)(smp + OFF_SBADJ);
    float* truep = (float*)(smp + OFF_TRUEP);
    float* rowh  = (float*)(smp + OFF_ROWH);
    int*   sidx  = (int*)(smp + OFF_SIDX);
    int*   ridx  = (int*)(smp + OFF_RIDX);
    int*   lidx  = (int*)(smp + OFF_LIDX);

    // ---- phase 0: index-width detect (warp 0) ----
    if (w == 0) {
        unsigned hi = ((const unsigned*)inp)[2 * lane + 1];
        unsigned bl = __ballot_sync(0xFFFFFFFFu, hi == 0u);
        if (lane == 0) *(int*)(smp + OFF_IS64) = (bl == 0xFFFFFFFFu) ? 1 : 0;
    }
    __syncthreads();
    const int is64 = *(const int*)(smp + OFF_IS64);

    // ---- phase 1: indices + sampled bias/log-adjust ----
    if (t < MROWS) {
        ridx[t] = load_idx(inp, b0 + t, is64);
        lidx[t] = load_idx(lab, b0 + t, is64);
    }
    {
        int sid = load_idx(samp, t, is64);
        sidx[t]  = sid;
        sbadj[t] = __ldg(&bias[sid]) - log_adj(sid);
    }
    __syncthreads();

    // ---- phase 2: gather embed -> d_out (fp32) + A tile (bf16); Wnce -> B ----
    {
        const float4* e4 = (const float4*)emb;
        float4* o4 = (float4*)out;
        #pragma unroll
        for (int i = 0; i < (MROWS * 64) / NTHR; i++) {          // 32 iters
            int lid = i * NTHR + t;
            int r = lid >> 6, c4 = lid & 63;
            float4 v = e4[(size_t)ridx[r] * 64 + c4];
            o4[(size_t)(b0 + r) * 64 + c4] = v;
            st4bf16(sb + OFF_A + (uint32_t)r * STRIDE + (uint32_t)c4 * 8u, v);
        }
        #pragma unroll
        for (int i = 0; i < (NS * 64) / NTHR; i++) {             // 64 iters
            int lid = i * NTHR + t;
            int s = lid >> 6, c4 = lid & 63;
            float4 v = ((const float4*)Wnce)[(size_t)sidx[s] * 64 + c4];
            st4bf16(sb + OFF_B + (uint32_t)s * STRIDE + (uint32_t)c4 * 8u, v);
        }
    }

    // ---- phase 3: true logits (exact fp32, L2-warm gathers), 16 rows/warp ----
    #pragma unroll
    for (int rr = 0; rr < 16; rr++) {
        int r = w * 16 + rr;
        int lbl = lidx[r];
        const float4* wr = (const float4*)(Wnce + (size_t)lbl * EMB);
        const float4* er = (const float4*)(emb + (size_t)ridx[r] * EMB);
        float s = 0.0f;
        #pragma unroll
        for (int j = 0; j < 2; j++) {
            float4 a = __ldg(&wr[lane + 32 * j]);
            float4 b = __ldg(&er[lane + 32 * j]);
            s += a.x * b.x + a.y * b.y + a.z * b.z + a.w * b.w;
        }
        #pragma unroll
        for (int o = 16; o; o >>= 1) s += __shfl_xor_sync(0xFFFFFFFFu, s, o);
        if (lane == 0) {
            float l = s + __ldg(&bias[lbl]) - log_adj(lbl);
            truep[r] = fmaxf(l, 0.0f) - l + log1pf(__expf(-fabsf(l)));
        }
    }
    __syncthreads();

    // ---- phase 4: sampled GEMM via mma.sync bf16 + fused xent epilogue ----
    // warp grid: 4 (M) x 2 (N-half); warp tile 32 rows x 128 cols, as two
    // 32x64 passes (acc stays at 64 regs).
    const int mrow0 = (w >> 1) * 32;
    const int nbase = (w & 1) * 128;

    // fragment base addrs: A[r][k] pair at r*STRIDE + k*2 (k even)
    const uint32_t Abase = sb + OFF_A + (uint32_t)(mrow0 + tq) * STRIDE + (uint32_t)tr * 4u;
    float rs[2][2] = {{0.f, 0.f}, {0.f, 0.f}};   // [m-subtile][row-in-pair]

    #pragma unroll 1
    for (int h = 0; h < 2; h++) {
        const int ncol0 = nbase + h * 64;
        const uint32_t Bbase = sb + OFF_B + (uint32_t)(ncol0 + tq) * STRIDE + (uint32_t)tr * 4u;

        float acc[2][8][4];
        #pragma unroll
        for (int m = 0; m < 2; m++)
            #pragma unroll
            for (int n = 0; n < 8; n++)
                #pragma unroll
                for (int c = 0; c < 4; c++) acc[m][n][c] = 0.0f;

        #pragma unroll 4
        for (int k = 0; k < 16; k++) {
            uint32_t a[2][4], bfr[8][2];
            const uint32_t ko = (uint32_t)k * 32u;
            #pragma unroll
            for (int m = 0; m < 2; m++) {
                uint32_t base = Abase + (uint32_t)m * (16u * STRIDE) + ko;
                a[m][0] = lds32(base);
                a[m][1] = lds32(base + 8u * STRIDE);
                a[m][2] = lds32(base + 16u);
                a[m][3] = lds32(base + 8u * STRIDE + 16u);
            }
            #pragma unroll
            for (int n = 0; n < 8; n++) {
                uint32_t base = Bbase + (uint32_t)n * (8u * STRIDE) + ko;
                bfr[n][0] = lds32(base);
                bfr[n][1] = lds32(base + 16u);
            }
            #pragma unroll
            for (int m = 0; m < 2; m++)
                #pragma unroll
                for (int n = 0; n < 8; n++)
                    MMA16816(acc[m][n], a[m], bfr[n]);
        }

        // epilogue: logits -> xent_neg -> per-row partial sums
        #pragma unroll
        for (int n = 0; n < 8; n++) {
            float2 badj = lds64f(sb + OFF_SBADJ + ((uint32_t)(ncol0 + n * 8 + tr * 2)) * 4u);
            #pragma unroll
            for (int m = 0; m < 2; m++) {
                rs[m][0] += xent_neg(acc[m][n][0] + badj.x) + xent_neg(acc[m][n][1] + badj.y);
                rs[m][1] += xent_neg(acc[m][n][2] + badj.x) + xent_neg(acc[m][n][3] + badj.y);
            }
        }
    }

    // reduce across the 4 lanes of each quad (same rows), then write rowh
    #pragma unroll
    for (int m = 0; m < 2; m++) {
        #pragma unroll
        for (int p = 0; p < 2; p++) {
            rs[m][p] += __shfl_xor_sync(0xFFFFFFFFu, rs[m][p], 1);
            rs[m][p] += __shfl_xor_sync(0xFFFFFFFFu, rs[m][p], 2);
        }
    }
    if (tr == 0) {
        int half = (w & 1) * 128;
        rowh[half + mrow0 + 0 * 16 + tq]     = rs[0][0];
        rowh[half + mrow0 + 0 * 16 + tq + 8] = rs[0][1];
        rowh[half + mrow0 + 1 * 16 + tq]     = rs[1][0];
        rowh[half + mrow0 + 1 * 16 + tq + 8] = rs[1][1];
    }
    __syncthreads();

    // ---- phase 5: per-row totals -> block partial ----
    if (t < MROWS) {
        float s = truep[t] + rowh[t] + rowh[128 + t];
        #pragma unroll
        for (int o = 16; o; o >>= 1) s += __shfl_xor_sync(0xFFFFFFFFu, s, o);
        if ((t & 31) == 0) ((float*)(smp + OFF_WSUM))[t >> 5] = s;
    }
    __syncthreads();
    if (t == 0) {
        const float* ws = (const float*)(smp + OFF_WSUM);
        g_partial[blockIdx.x] = (ws[0] + ws[1]) + (ws[2] + ws[3]);
    }
}

// deterministic fixed-order final reduction; cost -> last output slot
__global__ void k_fin(float* __restrict__ out, int out_size) {
    __shared__ float ss[4];
    int t = threadIdx.x;                 // 128 threads
    float s = g_partial[t];
    #pragma unroll
    for (int o = 16; o; o >>= 1) s += __shfl_xor_sync(0xFFFFFFFFu, s, o);
    if ((t & 31) == 0) ss[t >> 5] = s;
    __syncthreads();
    if (t == 0) out[out_size - 1] = ((ss[0] + ss[1]) + (ss[2] + ss[3])) / (float)BATCHN;
}

extern "C" void kernel_launch(void* const* d_in, const int* in_sizes, int n_in,
                              void* d_out, int out_size) {
    const float* emb  = (const float*)d_in[0];
    const float* Wnce = (const float*)d_in[1];
    const float* bias = (const float*)d_in[2];
    const void*  inp  = d_in[3];
    const void*  lab  = d_in[4];
    const void*  samp = d_in[5];
    float* out = (float*)d_out;

    cudaFuncSetAttribute(k_main, cudaFuncAttributeMaxDynamicSharedMemorySize, SMEM_BYTES);
    k_main<<<NBLK, NTHR, SMEM_BYTES>>>(emb, Wnce, bias, inp, lab, samp, out);
    k_fin<<<1, 128>>>(out, out_size);
}